// round 9
// baseline (speedup 1.0000x reference)
#include <cuda_runtime.h>
#include <math.h>
#include <stdint.h>

#define NB    8192      // batch
#define DK    768       // key dim
#define DIM   768       // embedding dim
#define POOL  30
#define PLEN  20
#define TOPK  5
#define HALF  10        // PLEN/2

// Scratch (no allocation allowed).
__device__ float g_nk[POOL * DK];
__device__ int   g_idx[NB * TOPK];

// ---------------------------------------------------------------------------
// Kernel 0: normalize K rows. 30 blocks x 32 threads (validated round 6).
// ---------------------------------------------------------------------------
__global__ __launch_bounds__(32) void norm_kernel(const float* __restrict__ K) {
    int w    = blockIdx.x;
    int lane = threadIdx.x;

    const float4* k4 = reinterpret_cast<const float4*>(K) + w * (DK / 4);
    float4 v[6];
    float ss = 0.0f;
#pragma unroll
    for (int j = 0; j < 6; j++) {
        v[j] = __ldg(k4 + j * 32 + lane);
        ss += v[j].x * v[j].x + v[j].y * v[j].y + v[j].z * v[j].z + v[j].w * v[j].w;
    }
#pragma unroll
    for (int off = 16; off; off >>= 1)
        ss += __shfl_xor_sync(0xFFFFFFFFu, ss, off);

    float inv = 1.0f / sqrtf(fmaxf(ss, 1e-24f));   // matches max(norm,1e-12)
    float4* o = reinterpret_cast<float4*>(g_nk) + w * (DK / 4);
#pragma unroll
    for (int j = 0; j < 6; j++) {
        float4 r = v[j];
        r.x *= inv; r.y *= inv; r.z *= inv; r.w *= inv;
        o[j * 32 + lane] = r;
    }
}

// ---------------------------------------------------------------------------
// Kernel 1: cosine-sim top-5, DK split across 2 warps.
// Block = 256 threads / 8 warps; warp (g,h): row-group g (4 rows) x dim-half h.
// Per-warp regs halved vs round 6 (q[4][3]) -> 2x latency-hiding parallelism.
// Butterfly truncated at 3 steps; 8 partials per (row,k) summed in phase 3.
// ---------------------------------------------------------------------------
__global__ __launch_bounds__(256) void topk_kernel(const float* __restrict__ xq) {
    const int lane = threadIdx.x & 31;
    const int wInB = threadIdx.x >> 5;     // 0..7
    const int g    = wInB >> 1;            // row group 0..3
    const int h    = wInB & 1;             // dim half 0..1
    const int row0 = blockIdx.x * 16 + g * 4;

    __shared__ float s_part[16][POOL][8];  // [localRow][k][half*4+residue]

    const float4* q4 = reinterpret_cast<const float4*>(xq);
    float4 q[4][3];
#pragma unroll
    for (int r = 0; r < 4; r++) {
        const float4* src = q4 + (size_t)(row0 + r) * (DK / 4) + h * (DK / 8);
#pragma unroll
        for (int j = 0; j < 3; j++)
            q[r][j] = __ldg(src + j * 32 + lane);
    }

    const float4* nk4 = reinterpret_cast<const float4*>(g_nk);
    for (int k = 0; k < POOL; k++) {
        float a0 = 0.f, a1 = 0.f, a2 = 0.f, a3 = 0.f;
        const float4* nk = nk4 + k * (DK / 4) + h * (DK / 8);
#pragma unroll
        for (int j = 0; j < 3; j++) {
            float4 n = __ldg(nk + j * 32 + lane);
            a0 += q[0][j].x * n.x + q[0][j].y * n.y + q[0][j].z * n.z + q[0][j].w * n.w;
            a1 += q[1][j].x * n.x + q[1][j].y * n.y + q[1][j].z * n.z + q[1][j].w * n.w;
            a2 += q[2][j].x * n.x + q[2][j].y * n.y + q[2][j].z * n.z + q[2][j].w * n.w;
            a3 += q[3][j].x * n.x + q[3][j].y * n.y + q[3][j].z * n.z + q[3][j].w * n.w;
        }
        // partial butterfly: 3 steps -> lane l (l<4) holds sum over lanes==l mod 4
#pragma unroll
        for (int off = 16; off >= 4; off >>= 1) {
            a0 += __shfl_xor_sync(0xFFFFFFFFu, a0, off);
            a1 += __shfl_xor_sync(0xFFFFFFFFu, a1, off);
            a2 += __shfl_xor_sync(0xFFFFFFFFu, a2, off);
            a3 += __shfl_xor_sync(0xFFFFFFFFu, a3, off);
        }
        if (lane < 4) {
            int slot = h * 4 + lane;
            int lg   = g * 4;
            s_part[lg + 0][k][slot] = a0;
            s_part[lg + 1][k][slot] = a1;
            s_part[lg + 2][k][slot] = a2;
            s_part[lg + 3][k][slot] = a3;
        }
    }
    __syncthreads();

    // ---------------- phase 3: finish reduction + serial top-5 --------------
    if (threadIdx.x < 16) {
        int lr  = threadIdx.x;
        int row = blockIdx.x * 16 + lr;
        float sims[POOL];
#pragma unroll
        for (int k = 0; k < POOL; k++) {
            float s01 = s_part[lr][k][0] + s_part[lr][k][1];
            float s23 = s_part[lr][k][2] + s_part[lr][k][3];
            float s45 = s_part[lr][k][4] + s_part[lr][k][5];
            float s67 = s_part[lr][k][6] + s_part[lr][k][7];
            sims[k] = (s01 + s23) + (s45 + s67);
        }
        unsigned used = 0;
#pragma unroll
        for (int t = 0; t < TOPK; t++) {
            float best = -3.4e38f;
            int   bi   = 0;
#pragma unroll
            for (int k = 0; k < POOL; k++) {
                if ((used >> k) & 1u) continue;
                float v = sims[k];
                if (v > best) { best = v; bi = k; }   // strict > => smallest idx ties
            }
            used |= (1u << bi);
            g_idx[row * TOPK + t] = bi;
        }
    }
}

// ---------------------------------------------------------------------------
// Kernel 2: gather — UNCHANGED validated version (92.7% DRAM, 7.35 TB/s).
// ---------------------------------------------------------------------------
__global__ __launch_bounds__(256) void gather_kernel(const float* __restrict__ p,
                                                     float* __restrict__ out) {
    int t = blockIdx.x;        // 0..4
    int b = blockIdx.y;        // 0..NB-1
    int k = g_idx[b * TOPK + t];

    const float4* src  = reinterpret_cast<const float4*>(p) + (size_t)k * (PLEN * DIM / 4);
    float4*       out4 = reinterpret_cast<float4*>(out);

    const size_t base0 = ((size_t)b * (TOPK * HALF) + (size_t)t * HALF) * (DIM / 4);
    const size_t base1 = ((size_t)(NB + b) * (TOPK * HALF) + (size_t)t * HALF) * (DIM / 4);
    const int    halfN = HALF * DIM / 4;   // 1920 float4 per half

#pragma unroll 5
    for (int i = threadIdx.x; i < PLEN * DIM / 4; i += 256) {
        float4 v = __ldg(src + i);
        if (i < halfN) out4[base0 + i] = v;
        else           out4[base1 + (i - halfN)] = v;
    }
}

// ---------------------------------------------------------------------------
extern "C" void kernel_launch(void* const* d_in, const int* in_sizes, int n_in,
                              void* d_out, int out_size) {
    const float* xq = (const float*)d_in[0];   // x_query [8192,768]
    // d_in[1] = x (unused)
    const float* K  = (const float*)d_in[2];   // [30,768]
    const float* p  = (const float*)d_in[3];   // [30,20,768]
    float*       out = (float*)d_out;          // [2,8192,50,768]

    norm_kernel<<<POOL, 32>>>(K);
    topk_kernel<<<NB / 16, 256>>>(xq);
    gather_kernel<<<dim3(TOPK, NB), 256>>>(p, out);
}

// round 10
// speedup vs baseline: 1.6685x; 1.6685x over previous
#include <cuda_runtime.h>
#include <math.h>
#include <stdint.h>

#define NB    8192      // batch
#define DK    768       // key dim
#define DIM   768       // embedding dim
#define POOL  30
#define PLEN  20
#define TOPK  5
#define HALF  10        // PLEN/2

// Scratch (no allocation allowed).
__device__ float g_nk[POOL * DK];
__device__ int   g_idx[NB * TOPK];

// ---------------------------------------------------------------------------
// Kernel 0: normalize K rows. 30 blocks x 32 threads (validated round 6).
// ---------------------------------------------------------------------------
__global__ __launch_bounds__(32) void norm_kernel(const float* __restrict__ K) {
    int w    = blockIdx.x;     // pool row
    int lane = threadIdx.x;

    const float4* k4 = reinterpret_cast<const float4*>(K) + w * (DK / 4);
    float4 v[6];
    float ss = 0.0f;
#pragma unroll
    for (int j = 0; j < 6; j++) {
        v[j] = __ldg(k4 + j * 32 + lane);
        ss += v[j].x * v[j].x + v[j].y * v[j].y + v[j].z * v[j].z + v[j].w * v[j].w;
    }
#pragma unroll
    for (int off = 16; off; off >>= 1)
        ss += __shfl_xor_sync(0xFFFFFFFFu, ss, off);

    float inv = 1.0f / sqrtf(fmaxf(ss, 1e-24f));   // matches max(norm,1e-12)
    float4* o = reinterpret_cast<float4*>(g_nk) + w * (DK / 4);
#pragma unroll
    for (int j = 0; j < 6; j++) {
        float4 r = v[j];
        r.x *= inv; r.y *= inv; r.z *= inv; r.w *= inv;
        o[j * 32 + lane] = r;
    }
}

// ---------------------------------------------------------------------------
// Kernel 1: cosine-sim top-5 (validated round 6, byte-identical).
// Block = 4 warps = 16 rows, one warp -> 4 rows, butterfly truncated at 3
// steps (lanes 0..3 hold residue-class partials; phase 3 finishes).
// ---------------------------------------------------------------------------
__global__ __launch_bounds__(128) void topk_kernel(const float* __restrict__ xq) {
    int lane = threadIdx.x & 31;
    int wInB = threadIdx.x >> 5;                  // warp in block (0..3)
    int row0 = blockIdx.x * 16;
    int rBase = wInB * 4;                         // local rows rBase..rBase+3

    __shared__ float s_part[16][POOL][4];         // [localRow][k][residue]

    const float4* q4 = reinterpret_cast<const float4*>(xq);
    float4 q[4][6];
#pragma unroll
    for (int r = 0; r < 4; r++) {
        const float4* src = q4 + (size_t)(row0 + rBase + r) * (DK / 4);
#pragma unroll
        for (int j = 0; j < 6; j++)
            q[r][j] = __ldg(src + j * 32 + lane);
    }

    const float4* nk4 = reinterpret_cast<const float4*>(g_nk);
    for (int k = 0; k < POOL; k++) {
        float a0 = 0.f, a1 = 0.f, a2 = 0.f, a3 = 0.f;
        const float4* nk = nk4 + k * (DK / 4);
#pragma unroll
        for (int j = 0; j < 6; j++) {
            float4 n = __ldg(nk + j * 32 + lane);
            a0 += q[0][j].x * n.x + q[0][j].y * n.y + q[0][j].z * n.z + q[0][j].w * n.w;
            a1 += q[1][j].x * n.x + q[1][j].y * n.y + q[1][j].z * n.z + q[1][j].w * n.w;
            a2 += q[2][j].x * n.x + q[2][j].y * n.y + q[2][j].z * n.z + q[2][j].w * n.w;
            a3 += q[3][j].x * n.x + q[3][j].y * n.y + q[3][j].z * n.z + q[3][j].w * n.w;
        }
        // partial butterfly: 3 steps -> lane l holds sum over lanes == l (mod 4)
#pragma unroll
        for (int off = 16; off >= 4; off >>= 1) {
            a0 += __shfl_xor_sync(0xFFFFFFFFu, a0, off);
            a1 += __shfl_xor_sync(0xFFFFFFFFu, a1, off);
            a2 += __shfl_xor_sync(0xFFFFFFFFu, a2, off);
            a3 += __shfl_xor_sync(0xFFFFFFFFu, a3, off);
        }
        if (lane < 4) {
            s_part[rBase + 0][k][lane] = a0;
            s_part[rBase + 1][k][lane] = a1;
            s_part[rBase + 2][k][lane] = a2;
            s_part[rBase + 3][k][lane] = a3;
        }
    }
    __syncthreads();

    // ---------------- phase 3: finish reduction + serial top-5 --------------
    if (threadIdx.x < 16) {
        int lr  = threadIdx.x;
        int row = row0 + lr;
        float sims[POOL];
#pragma unroll
        for (int k = 0; k < POOL; k++) {
            sims[k] = (s_part[lr][k][0] + s_part[lr][k][1])
                    + (s_part[lr][k][2] + s_part[lr][k][3]);
        }
        unsigned used = 0;
#pragma unroll
        for (int t = 0; t < TOPK; t++) {
            float best = -3.4e38f;
            int   bi   = 0;
#pragma unroll
            for (int k = 0; k < POOL; k++) {
                if ((used >> k) & 1u) continue;
                float v = sims[k];
                if (v > best) { best = v; bi = k; }   // strict > => smallest idx on ties
            }
            used |= (1u << bi);
            g_idx[row * TOPK + t] = bi;
        }
    }
}

// ---------------------------------------------------------------------------
// Kernel 2: gather — round-6 body, single change: __stcs streaming stores so
// the 2.52GB output stream is evict-first in L2 (protects the 1.84MB p set).
// ---------------------------------------------------------------------------
__global__ __launch_bounds__(256) void gather_kernel(const float* __restrict__ p,
                                                     float* __restrict__ out) {
    int t = blockIdx.x;        // 0..4
    int b = blockIdx.y;        // 0..NB-1
    int k = g_idx[b * TOPK + t];

    const float4* src  = reinterpret_cast<const float4*>(p) + (size_t)k * (PLEN * DIM / 4);
    float4*       out4 = reinterpret_cast<float4*>(out);

    const size_t base0 = ((size_t)b * (TOPK * HALF) + (size_t)t * HALF) * (DIM / 4);
    const size_t base1 = ((size_t)(NB + b) * (TOPK * HALF) + (size_t)t * HALF) * (DIM / 4);
    const int    halfN = HALF * DIM / 4;   // 1920 float4 per half

#pragma unroll 5
    for (int i = threadIdx.x; i < PLEN * DIM / 4; i += 256) {
        float4 v = __ldg(src + i);
        if (i < halfN) __stcs(out4 + base0 + i, v);
        else           __stcs(out4 + base1 + (i - halfN), v);
    }
}

// ---------------------------------------------------------------------------
extern "C" void kernel_launch(void* const* d_in, const int* in_sizes, int n_in,
                              void* d_out, int out_size) {
    const float* xq = (const float*)d_in[0];   // x_query [8192,768]
    // d_in[1] = x (unused)
    const float* K  = (const float*)d_in[2];   // [30,768]
    const float* p  = (const float*)d_in[3];   // [30,20,768]
    float*       out = (float*)d_out;          // [2,8192,50,768]

    norm_kernel<<<POOL, 32>>>(K);
    topk_kernel<<<NB / 16, 128>>>(xq);
    gather_kernel<<<dim3(TOPK, NB), 256>>>(p, out);
}

// round 13
// speedup vs baseline: 1.6708x; 1.0013x over previous
#include <cuda_runtime.h>
#include <math.h>
#include <stdint.h>

#define NB    8192      // batch
#define DK    768       // key dim
#define DIM   768       // embedding dim
#define POOL  30
#define PLEN  20
#define TOPK  5
#define HALF  10        // PLEN/2

// Scratch (no allocation allowed).
__device__ int g_idx[NB * TOPK];

// ---------------------------------------------------------------------------
// Kernel 1: fused norm + cosine-sim + top-5.
// Round-6 validated structure (4 warps, one warp -> 4 rows, truncated
// butterfly), with dot(K_k,K_k) computed inside the sim loop on K fragments
// already in registers (round-7 validated numerics: sim = a * rsqrt(s)).
// Eliminates the norm kernel and one launch gap.
// ---------------------------------------------------------------------------
__global__ __launch_bounds__(128) void topk_kernel(const float* __restrict__ xq,
                                                   const float* __restrict__ K) {
    int lane = threadIdx.x & 31;
    int wInB = threadIdx.x >> 5;                  // warp in block (0..3)
    int row0 = blockIdx.x * 16;
    int rBase = wInB * 4;                         // local rows rBase..rBase+3

    __shared__ float s_part[16][POOL][4];         // [localRow][k][residue] (dot partials)
    __shared__ float s_norm[POOL][4];             // [k][residue] (||K_k||^2 partials)

    const float4* q4 = reinterpret_cast<const float4*>(xq);
    float4 q[4][6];
#pragma unroll
    for (int r = 0; r < 4; r++) {
        const float4* src = q4 + (size_t)(row0 + rBase + r) * (DK / 4);
#pragma unroll
        for (int j = 0; j < 6; j++)
            q[r][j] = __ldg(src + j * 32 + lane);
    }

    const float4* K4 = reinterpret_cast<const float4*>(K);
    for (int k = 0; k < POOL; k++) {
        float a0 = 0.f, a1 = 0.f, a2 = 0.f, a3 = 0.f;
        float s  = 0.f;                           // dot(K_k, K_k)
        const float4* nk = K4 + k * (DK / 4);
#pragma unroll
        for (int j = 0; j < 6; j++) {
            float4 n = __ldg(nk + j * 32 + lane);
            a0 += q[0][j].x * n.x + q[0][j].y * n.y + q[0][j].z * n.z + q[0][j].w * n.w;
            a1 += q[1][j].x * n.x + q[1][j].y * n.y + q[1][j].z * n.z + q[1][j].w * n.w;
            a2 += q[2][j].x * n.x + q[2][j].y * n.y + q[2][j].z * n.z + q[2][j].w * n.w;
            a3 += q[3][j].x * n.x + q[3][j].y * n.y + q[3][j].z * n.z + q[3][j].w * n.w;
            s  += n.x * n.x + n.y * n.y + n.z * n.z + n.w * n.w;
        }
        // partial butterflies: 3 steps -> lane l (l<4) holds sum over lanes==l mod 4
#pragma unroll
        for (int off = 16; off >= 4; off >>= 1) {
            a0 += __shfl_xor_sync(0xFFFFFFFFu, a0, off);
            a1 += __shfl_xor_sync(0xFFFFFFFFu, a1, off);
            a2 += __shfl_xor_sync(0xFFFFFFFFu, a2, off);
            a3 += __shfl_xor_sync(0xFFFFFFFFu, a3, off);
            s  += __shfl_xor_sync(0xFFFFFFFFu, s,  off);
        }
        if (lane < 4) {
            s_part[rBase + 0][k][lane] = a0;
            s_part[rBase + 1][k][lane] = a1;
            s_part[rBase + 2][k][lane] = a2;
            s_part[rBase + 3][k][lane] = a3;
            if (wInB == 0) s_norm[k][lane] = s;   // all warps compute identical s
        }
    }
    __syncthreads();

    // ---------------- phase 3: finish reductions + serial top-5 -------------
    if (threadIdx.x < 16) {
        int lr  = threadIdx.x;
        int row = row0 + lr;
        float sims[POOL];
#pragma unroll
        for (int k = 0; k < POOL; k++) {
            float a = (s_part[lr][k][0] + s_part[lr][k][1])
                    + (s_part[lr][k][2] + s_part[lr][k][3]);
            float s = (s_norm[k][0] + s_norm[k][1])
                    + (s_norm[k][2] + s_norm[k][3]);
            sims[k] = a * (1.0f / sqrtf(fmaxf(s, 1e-24f)));  // = a / max(||K||,1e-12)
        }
        unsigned used = 0;
#pragma unroll
        for (int t = 0; t < TOPK; t++) {
            float best = -3.4e38f;
            int   bi   = 0;
#pragma unroll
            for (int k = 0; k < POOL; k++) {
                if ((used >> k) & 1u) continue;
                float v = sims[k];
                if (v > best) { best = v; bi = k; }   // strict > => smallest idx on ties
            }
            used |= (1u << bi);
            g_idx[row * TOPK + t] = bi;
        }
    }
}

// ---------------------------------------------------------------------------
// Kernel 2: gather — UNCHANGED round-10 version (__stcs, ~96% of write spec).
// ---------------------------------------------------------------------------
__global__ __launch_bounds__(256) void gather_kernel(const float* __restrict__ p,
                                                     float* __restrict__ out) {
    int t = blockIdx.x;        // 0..4
    int b = blockIdx.y;        // 0..NB-1
    int k = g_idx[b * TOPK + t];

    const float4* src  = reinterpret_cast<const float4*>(p) + (size_t)k * (PLEN * DIM / 4);
    float4*       out4 = reinterpret_cast<float4*>(out);

    const size_t base0 = ((size_t)b * (TOPK * HALF) + (size_t)t * HALF) * (DIM / 4);
    const size_t base1 = ((size_t)(NB + b) * (TOPK * HALF) + (size_t)t * HALF) * (DIM / 4);
    const int    halfN = HALF * DIM / 4;   // 1920 float4 per half

#pragma unroll 5
    for (int i = threadIdx.x; i < PLEN * DIM / 4; i += 256) {
        float4 v = __ldg(src + i);
        if (i < halfN) __stcs(out4 + base0 + i, v);
        else           __stcs(out4 + base1 + (i - halfN), v);
    }
}

// ---------------------------------------------------------------------------
extern "C" void kernel_launch(void* const* d_in, const int* in_sizes, int n_in,
                              void* d_out, int out_size) {
    const float* xq = (const float*)d_in[0];   // x_query [8192,768]
    // d_in[1] = x (unused)
    const float* K  = (const float*)d_in[2];   // [30,768]
    const float* p  = (const float*)d_in[3];   // [30,20,768]
    float*       out = (float*)d_out;          // [2,8192,50,768]

    topk_kernel<<<NB / 16, 128>>>(xq, K);
    gather_kernel<<<dim3(TOPK, NB), 256>>>(p, out);
}